// round 7
// baseline (speedup 1.0000x reference)
#include <cuda_runtime.h>
#include <math.h>
#include <float.h>

#define BB 16
#define SS 64
#define MM 2048
#define DD 256
#define TK 8
#define OV 512
#define NB 128
#define SCALE 0.0625f

// ---- persistent state (re-initialized every launch; no runtime allocs) ----
__device__ float g_ovl[BB*OV*DD];     // copy-on-write overlay rows
__device__ int   g_slot[BB*MM];
__device__ int   g_ovcnt[BB];
__device__ float g_qk[SS*BB*DD];      // scale*(Wk^T Wq x_t + Wk^T bq)
__device__ float g_gx[SS*BB*DD];      // Wu1 x_t + bu
__device__ float g_AT[DD*DD];         // [j][d] = SCALE * sum_i Wk[i][d] Wq[i][j]
__device__ float g_avec[DD];
__device__ float g_WuT1[DD*DD];       // [j][d] = Wu[d][j]
__device__ float g_WvT[DD*DD];        // [j][d] = Wv[d][j]
__device__ float g_W2c[DD*DD];        // [i][d] = sum_j Wv[j][i] Wu[d][DD+j]
__device__ float g_cvec[DD];          // [d] = sum_j bv[j] Wu[d][DD+j]
__device__ float g_scores[BB*MM];
__device__ float g_psum[NB*BB];       // per-block unnormalized exp sums
__device__ float g_partial[NB*BB*DD];
__device__ int   g_count;
__device__ int   g_gen2;

// =================== init launch 1 ===================
__global__ void p_init1(const float* __restrict__ Wq, const float* __restrict__ bq,
                        const float* __restrict__ Wk, const float* __restrict__ Wv,
                        const float* __restrict__ bv, const float* __restrict__ Wu){
  int blk = blockIdx.x, tid = threadIdx.x;
  if (blk < 32){                       // WvT[j][d] = Wv[d][j]
    int base = blk*2048;
    #pragma unroll
    for (int z=0;z<8;z++){ int e = base + z*256 + tid; int d = e>>8, j = e&255;
      g_WvT[j*DD+d] = Wv[(size_t)d*DD+j]; }
  } else if (blk < 64){                // WuT1[j][d] = Wu[d][j]
    int base = (blk-32)*2048;
    #pragma unroll
    for (int z=0;z<8;z++){ int e = base + z*256 + tid; int d = e>>8, j = e&255;
      g_WuT1[j*DD+d] = Wu[(size_t)d*2*DD + j]; }
  } else if (blk < 80){                // A tiles: g_AT[j][d]
    __shared__ float aq[16][68], ak[16][68];
    int tn = blk-64, j0 = (tn>>2)*64, d0 = (tn&3)*64;
    int ty = tid>>4, tx = tid&15;
    float acc[16];
    #pragma unroll
    for (int z=0;z<16;z++) acc[z]=0.f;
    for (int ib=0; ib<DD; ib+=16){
      #pragma unroll
      for (int z=0;z<4;z++){ int e = z*256+tid; int i=e>>6, j=e&63;
        aq[i][j] = Wq[(size_t)(ib+i)*DD + j0 + j];
        ak[i][j] = Wk[(size_t)(ib+i)*DD + d0 + j]; }
      __syncthreads();
      #pragma unroll
      for (int i=0;i<16;i++){
        float qv[4], kv[4];
        #pragma unroll
        for (int u=0;u<4;u++){ qv[u]=aq[i][ty*4+u]; kv[u]=ak[i][tx*4+u]; }
        #pragma unroll
        for (int jr=0;jr<4;jr++)
          #pragma unroll
          for (int dr=0;dr<4;dr++) acc[jr*4+dr] = fmaf(qv[jr], kv[dr], acc[jr*4+dr]);
      }
      __syncthreads();
    }
    #pragma unroll
    for (int jr=0;jr<4;jr++)
      #pragma unroll
      for (int dr=0;dr<4;dr++)
        g_AT[(size_t)(j0+ty*4+jr)*DD + d0+tx*4+dr] = acc[jr*4+dr]*SCALE;
  } else if (blk < 96){                // W2c tiles
    __shared__ float wv[16][68], wu[16][68];
    int tn = blk-80, i0 = (tn>>2)*64, d0 = (tn&3)*64;
    int ty = tid>>4, tx = tid&15;
    float acc[16];
    #pragma unroll
    for (int z=0;z<16;z++) acc[z]=0.f;
    for (int jb=0; jb<DD; jb+=16){
      #pragma unroll
      for (int z=0;z<4;z++){ int e = z*256+tid; int jj=e>>6, ii=e&63;
        wv[jj][ii] = Wv[(size_t)(jb+jj)*DD + i0 + ii];
        wu[jj][ii] = Wu[(size_t)(d0+ii)*2*DD + DD + jb + jj]; }
      __syncthreads();
      #pragma unroll
      for (int jj=0;jj<16;jj++){
        float vv[4], uv[4];
        #pragma unroll
        for (int u=0;u<4;u++){ vv[u]=wv[jj][ty*4+u]; uv[u]=wu[jj][tx*4+u]; }
        #pragma unroll
        for (int ir=0;ir<4;ir++)
          #pragma unroll
          for (int dr=0;dr<4;dr++) acc[ir*4+dr] = fmaf(vv[ir], uv[dr], acc[ir*4+dr]);
      }
      __syncthreads();
    }
    #pragma unroll
    for (int ir=0;ir<4;ir++)
      #pragma unroll
      for (int dr=0;dr<4;dr++)
        g_W2c[(size_t)(i0+ty*4+ir)*DD + d0+tx*4+dr] = acc[ir*4+dr];
  } else if (blk < 112){               // slot map
    int base = (blk-96)*2048;
    #pragma unroll
    for (int z=0;z<8;z++) g_slot[base + z*256 + tid] = -1;
  } else if (blk == 112){
    if (tid==0){ g_count = 0; g_gen2 = 0; }
    if (tid < BB) g_ovcnt[tid] = 0;
  } else if (blk == 113){              // avec
    __shared__ float bqs[DD];
    bqs[tid] = bq[tid]; __syncthreads();
    float acc = 0.f;
    #pragma unroll 4
    for (int i=0;i<DD;i++) acc = fmaf(Wk[(size_t)i*DD+tid], bqs[i], acc);
    g_avec[tid] = acc*SCALE;
  } else if (blk == 114){              // cvec
    __shared__ float bvs[DD];
    bvs[tid] = bv[tid]; __syncthreads();
    float acc = 0.f;
    #pragma unroll 4
    for (int j=0;j<DD;j++) acc = fmaf(Wu[(size_t)tid*2*DD + DD + j], bvs[j], acc);
    g_cvec[tid] = acc;
  }
}

// =================== init launch 2: qk / gx GEMMs ===================
__global__ void p_init2(const float* __restrict__ x, const float* __restrict__ bu){
  __shared__ float xt[64][17];
  __shared__ float wt[16][68];
  int blk = blockIdx.x, tid = threadIdx.x;
  int which = blk>>6;
  int r = blk&63;
  int s0 = (r>>2)*64, d0 = (r&3)*64;
  const float* W = which ? g_WuT1 : g_AT;
  int ty = tid>>4, tx = tid&15;
  float acc[16];
  #pragma unroll
  for (int z=0;z<16;z++) acc[z]=0.f;
  for (int jb=0; jb<DD; jb+=16){
    { int ss = tid>>2, jq = tid&3;
      float4 xv = *(const float4*)&x[(size_t)(s0+ss)*DD + jb + jq*4];
      xt[ss][jq*4+0]=xv.x; xt[ss][jq*4+1]=xv.y; xt[ss][jq*4+2]=xv.z; xt[ss][jq*4+3]=xv.w; }
    #pragma unroll
    for (int z=0;z<4;z++){ int e = z*256+tid; int jj=e>>6, dd=e&63;
      wt[jj][dd] = W[(size_t)(jb+jj)*DD + d0 + dd]; }
    __syncthreads();
    #pragma unroll
    for (int jj=0;jj<16;jj++){
      float xv[4], wv4[4];
      #pragma unroll
      for (int u=0;u<4;u++){ xv[u]=xt[ty*4+u][jj]; wv4[u]=wt[jj][tx*4+u]; }
      #pragma unroll
      for (int sr=0;sr<4;sr++)
        #pragma unroll
        for (int dr=0;dr<4;dr++) acc[sr*4+dr] = fmaf(xv[sr], wv4[dr], acc[sr*4+dr]);
    }
    __syncthreads();
  }
  float* dst = which ? g_gx : g_qk;
  const float* bias = which ? bu : g_avec;
  #pragma unroll
  for (int sr=0;sr<4;sr++){
    int s = s0 + ty*4 + sr;
    int b = s>>6, t = s&63;
    size_t ro = (size_t)(t*BB+b)*DD + d0 + tx*4;
    #pragma unroll
    for (int dr=0;dr<4;dr++) dst[ro+dr] = acc[sr*4+dr] + bias[d0+tx*4+dr];
  }
}

// =================== grid barrier ===================
__device__ __forceinline__ void gbar(int target){
  __syncthreads();
  if (threadIdx.x == 0){
    int old;
    asm volatile("atom.acq_rel.gpu.global.add.s32 %0, [%1], %2;"
                 : "=r"(old) : "l"(&g_count), "r"(1) : "memory");
    if (old == target*NB - 1){
      asm volatile("st.release.gpu.global.s32 [%0], %1;"
                   :: "l"(&g_gen2), "r"(target) : "memory");
    } else {
      int g;
      do {
        asm volatile("ld.acquire.gpu.global.s32 %0, [%1];"
                     : "=r"(g) : "l"(&g_gen2) : "memory");
      } while (g < target);
    }
  }
  __syncthreads();
}

__device__ __forceinline__ float dot4acc(float4 a, float4 b, float acc){
  acc = fmaf(a.x, b.x, acc);
  acc = fmaf(a.y, b.y, acc);
  acc = fmaf(a.z, b.z, acc);
  acc = fmaf(a.w, b.w, acc);
  return acc;
}

// =================== the persistent kernel ===================
__global__ void __launch_bounds__(256, 1)
persist(const float* __restrict__ base, const float* __restrict__ x,
        const float* __restrict__ bv, float* __restrict__ out){
  extern __shared__ float dsm[];
  float* rowsf  = dsm;                 // 16*256
  float* qk2f   = dsm + 4096;          // 16*256
  float* spartf = dsm + 8192;          // 16*256

  __shared__ float sc[16][17];
  __shared__ __align__(16) float attn_s[16][24];   // unnormalized e
  __shared__ int   dlist[256];
  __shared__ int   dcnt_s;
  __shared__ float warrv[8]; __shared__ int warri[8];
  __shared__ int   idxs_s[TK];
  __shared__ int   chosen_s;
  __shared__ float zred[4];
  __shared__ float zinv_s;
  __shared__ __align__(16) float4 h4[4][64];
  __shared__ __align__(16) float4 hs4[64];
  __shared__ float gates_s[DD];
  __shared__ int   rowss[TK], prevs[TK], slots[TK];

  int blk = blockIdx.x, tid = threadIdx.x;
  int m0 = blk*16;
  int wid = tid>>5, lane = tid&31;

  // base rows resident for the whole run
  for (int i=tid;i<16*DD;i+=256) rowsf[i] = base[(size_t)m0*DD + i];
  // qk for t=0
  for (int i=tid;i<16*DD;i+=256) qk2f[i] = g_qk[i];

  int bid = 0;
  for (int t=0;t<SS;t++){
    // ========== Phase AB: scores + exp + partials ==========
    if (tid==0) dcnt_s = 0;
    __syncthreads();
    {
      int b = tid>>4, r = tid&15;
      int s = __ldcg(&g_slot[b*MM + m0 + r]);
      if (s >= 0){ int p = atomicAdd(&dcnt_s,1); dlist[p] = (b<<16)|(r<<12)|s; }
    }
    // base score GEMM: 16b x 16r x 256j, j split 16 ways, 4x4 outputs
    {
      int jq = tid&15, bq0 = ((tid>>4)&3)*4, r0 = (tid>>6)*4;
      float acc[16];
      #pragma unroll
      for (int zz=0;zz<16;zz++) acc[zz]=0.f;
      #pragma unroll
      for (int jj=0;jj<4;jj++){
        int jb = jj*64 + jq*4;
        float4 qa[4], ra[4];
        #pragma unroll
        for (int u=0;u<4;u++){
          qa[u] = *(const float4*)&qk2f[(bq0+u)*256 + jb];
          ra[u] = *(const float4*)&rowsf[(r0+u)*256 + jb];
        }
        #pragma unroll
        for (int bi=0;bi<4;bi++)
          #pragma unroll
          for (int ri=0;ri<4;ri++)
            acc[bi*4+ri] = dot4acc(qa[bi], ra[ri], acc[bi*4+ri]);
      }
      #pragma unroll
      for (int off=8; off; off>>=1){
        #pragma unroll
        for (int zz=0;zz<16;zz++) acc[zz] += __shfl_xor_sync(0xffffffffu, acc[zz], off);
      }
      if (jq==0){
        #pragma unroll
        for (int bi=0;bi<4;bi++)
          #pragma unroll
          for (int ri=0;ri<4;ri++) sc[bq0+bi][r0+ri] = acc[bi*4+ri];
      }
    }
    __syncthreads();
    int dn = dcnt_s;
    // dirty score fix (overlay rows)
    for (int e=wid; e<dn; e+=8){
      int pk = dlist[e]; int eb = pk>>16, er = (pk>>12)&15, es = pk&0xfff;
      const float* ov = g_ovl + ((size_t)eb*OV + es)*DD;
      float a2 = 0.f;
      #pragma unroll
      for (int k=0;k<8;k++) a2 = fmaf(__ldcg(&ov[lane+32*k]), qk2f[eb*256 + lane+32*k], a2);
      #pragma unroll
      for (int off=16; off; off>>=1) a2 += __shfl_xor_sync(0xffffffffu, a2, off);
      if (lane==0) sc[eb][er] = a2;
    }
    __syncthreads();
    // final scores -> gmem; e = exp(s); block psum per batch
    {
      int b = tid>>4, r = tid&15;
      float sv = sc[b][r];
      __stcg(&g_scores[b*MM + m0 + r], sv);
      float e = expf(sv);
      attn_s[b][r] = e;
      float ps = e;
      #pragma unroll
      for (int off=8; off; off>>=1) ps += __shfl_xor_sync(0xffffffffu, ps, off);
      if (r==0) __stcg(&g_psum[blk*16 + b], ps);
    }
    __syncthreads();
    // partials: spart[b][d] = sum_r e[b][r]*rows[r][d]
    {
      float rv[16];
      #pragma unroll
      for (int rr=0;rr<16;rr++) rv[rr] = rowsf[rr*256 + tid];
      #pragma unroll
      for (int bz=0;bz<16;bz++){
        float4 a0 = *(const float4*)&attn_s[bz][0];
        float4 a1 = *(const float4*)&attn_s[bz][4];
        float4 a2v= *(const float4*)&attn_s[bz][8];
        float4 a3 = *(const float4*)&attn_s[bz][12];
        float acc =  a0.x*rv[0]+a0.y*rv[1]+a0.z*rv[2]+a0.w*rv[3];
        acc = fmaf(a1.x,rv[4],acc);  acc = fmaf(a1.y,rv[5],acc);
        acc = fmaf(a1.z,rv[6],acc);  acc = fmaf(a1.w,rv[7],acc);
        acc = fmaf(a2v.x,rv[8],acc); acc = fmaf(a2v.y,rv[9],acc);
        acc = fmaf(a2v.z,rv[10],acc);acc = fmaf(a2v.w,rv[11],acc);
        acc = fmaf(a3.x,rv[12],acc); acc = fmaf(a3.y,rv[13],acc);
        acc = fmaf(a3.z,rv[14],acc); acc = fmaf(a3.w,rv[15],acc);
        spartf[bz*256 + tid] = acc;
      }
    }
    __syncthreads();
    // dirty partial corrections
    for (int e=wid; e<dn; e+=8){
      int pk = dlist[e]; int eb = pk>>16, er = (pk>>12)&15, es = pk&0xfff;
      const float* ov = g_ovl + ((size_t)eb*OV + es)*DD;
      float a = attn_s[eb][er];
      #pragma unroll
      for (int k=0;k<8;k++){
        int d = lane+32*k;
        atomicAdd(&spartf[eb*256 + d], a*(__ldcg(&ov[d]) - rowsf[er*256 + d]));
      }
    }
    __syncthreads();
    // store partials (float4, coalesced)
    {
      const float4* sp4 = (const float4*)spartf;
      float4* gp4 = (float4*)g_partial;
      #pragma unroll
      for (int z=0;z<4;z++) __stcg(&gp4[(size_t)blk*1024 + z*256 + tid], sp4[z*256 + tid]);
    }
    gbar(++bid);

    // ========== Phase C: per-batch finalize (16 blocks) ==========
    if (blk < BB){
      int b2 = blk;
      // Z
      float zp = (tid < NB) ? __ldcg(&g_psum[tid*BB + b2]) : 0.f;
      #pragma unroll
      for (int off=16; off; off>>=1) zp += __shfl_xor_sync(0xffffffffu, zp, off);
      if (lane==0 && wid<4) zred[wid] = zp;
      // h partial reduce (float4)
      {
        int d4 = tid&63, kg = tid>>6;
        const float4* gp4 = (const float4*)g_partial;
        float4 hv = make_float4(0.f,0.f,0.f,0.f);
        #pragma unroll 8
        for (int k=kg*32; k<kg*32+32; k++){
          float4 v = __ldcg(&gp4[(size_t)(k*16+b2)*64 + d4]);
          hv.x += v.x; hv.y += v.y; hv.z += v.z; hv.w += v.w;
        }
        h4[kg][d4] = hv;
      }
      __syncthreads();
      if (tid==0) zinv_s = 1.0f/(zred[0]+zred[1]+zred[2]+zred[3]);
      __syncthreads();
      if (tid < 64){
        float zi = zinv_s;
        float4 a = h4[0][tid], b = h4[1][tid], c = h4[2][tid], d = h4[3][tid];
        float4 s;
        s.x = (a.x+b.x+c.x+d.x)*zi;
        s.y = (a.y+b.y+c.y+d.y)*zi;
        s.z = (a.z+b.z+c.z+d.z)*zi;
        s.w = (a.w+b.w+c.w+d.w)*zi;
        hs4[tid] = s;
      }
      __syncthreads();
      // GEMVs: memout + gate preact
      {
        const float* hsf = (const float*)hs4;
        int d = tid;
        float mo = 0.f, gp = 0.f;
        #pragma unroll 8
        for (int j=0;j<DD;j++){
          float hj = hsf[j];
          mo = fmaf(g_WvT[j*DD+d], hj, mo);
          gp = fmaf(g_W2c[j*DD+d], hj, gp);
        }
        mo += bv[d];
        out[((size_t)b2*SS+t)*DD + d] = mo;
        float gg = g_gx[(size_t)(t*BB+b2)*DD + d] + g_cvec[d] + gp;
        gates_s[d] = 1.0f/(1.0f+expf(-gg));
      }
      // top-8
      {
        float4 va = __ldcg((const float4*)&g_scores[b2*MM + tid*8]);
        float4 vb = __ldcg((const float4*)&g_scores[b2*MM + tid*8 + 4]);
        float vloc[8] = {va.x,va.y,va.z,va.w,vb.x,vb.y,vb.z,vb.w};
        int base_m = tid*8;
        for (int round=0; round<TK; round++){
          float v = -FLT_MAX; int bi2 = MM;
          #pragma unroll
          for (int k=0;k<8;k++){ if (vloc[k] > v){ v = vloc[k]; bi2 = base_m+k; } }
          #pragma unroll
          for (int off=16; off; off>>=1){
            float ov2 = __shfl_xor_sync(0xffffffffu, v, off);
            int   oi  = __shfl_xor_sync(0xffffffffu, bi2, off);
            if (ov2 > v || (ov2==v && oi<bi2)){ v=ov2; bi2=oi; }
          }
          if (lane==0){ warrv[wid]=v; warri[wid]=bi2; }
          __syncthreads();
          if (tid==0){
            float bv2 = warrv[0]; int bj = warri[0];
            for (int w=1;w<8;w++){
              if (warrv[w]>bv2 || (warrv[w]==bv2 && warri[w]<bj)){ bv2=warrv[w]; bj=warri[w]; }
            }
            idxs_s[round] = bj; chosen_s = bj;
          }
          __syncthreads();
          int ch = chosen_s;
          if ((ch>>3) == tid) vloc[ch&7] = -FLT_MAX;
        }
      }
      // slot assignment
      if (tid==0){
        int cnt = __ldcg(&g_ovcnt[b2]);
        for (int i=0;i<TK;i++){
          int row = idxs_s[i];
          int s = __ldcg(&g_slot[b2*MM+row]);
          prevs[i] = s;
          if (s < 0){ s = cnt++; __stcg(&g_slot[b2*MM+row], s); }
          slots[i] = s; rowss[i] = row;
        }
        __stcg(&g_ovcnt[b2], cnt);
      }
      __syncthreads();
      // row updates: warp i handles updated row i
      if (wid < TK){
        int row = rowss[wid], prev = prevs[wid], slot = slots[wid];
        #pragma unroll
        for (int k=0;k<8;k++){
          int d = lane + 32*k;
          float old = (prev < 0) ? base[(size_t)row*DD + d]
                                 : __ldcg(&g_ovl[((size_t)b2*OV + prev)*DD + d]);
          float g = gates_s[d];
          float xd = x[((size_t)b2*SS+t)*DD + d];
          __stcg(&g_ovl[((size_t)b2*OV + slot)*DD + d], old + g*(xd - old));
        }
      }
    }
    // all blocks: prefetch next step's qk into smem
    if (t+1 < SS){
      const float* qsrc = g_qk + (size_t)(t+1)*BB*DD;
      for (int i=tid;i<16*DD;i+=256) qk2f[i] = qsrc[i];
    }
    gbar(++bid);
  }
}

// =================== launch ===================
extern "C" void kernel_launch(void* const* d_in, const int* in_sizes, int n_in,
                              void* d_out, int out_size){
  const float* x      = (const float*)d_in[0];
  const float* memory = (const float*)d_in[1];
  const float* Wq     = (const float*)d_in[2];
  const float* bq     = (const float*)d_in[3];
  const float* Wk     = (const float*)d_in[4];
  // bk contributes only a softmax-invariant constant -> dropped
  const float* Wv     = (const float*)d_in[6];
  const float* bv     = (const float*)d_in[7];
  const float* Wu     = (const float*)d_in[8];
  const float* bu     = (const float*)d_in[9];
  float* out = (float*)d_out;

  static int attr_done = 0;
  if (!attr_done){
    cudaFuncSetAttribute(persist, cudaFuncAttributeMaxDynamicSharedMemorySize, 49152);
    attr_done = 1;
  }

  p_init1<<<NB, 256>>>(Wq, bq, Wk, Wv, bv, Wu);
  p_init2<<<NB, 256>>>(x, bu);
  persist<<<NB, 256, 49152>>>(memory, x, bv, out);
}

// round 8
// speedup vs baseline: 1.2565x; 1.2565x over previous
#include <cuda_runtime.h>
#include <math.h>
#include <float.h>

#define BB 16
#define SS 64
#define MM 2048
#define DD 256
#define TK 8
#define OV 512
#define NB 128
#define SCALE 0.0625f

// ---- persistent state (re-initialized every launch; no runtime allocs) ----
__device__ float g_ovl[BB*OV*DD];
__device__ int   g_slot[BB*MM];
__device__ int   g_ovcnt[BB];
__device__ float g_qk[SS*BB*DD];      // [t][b][d]
__device__ float g_gx[SS*BB*DD];      // [t][b][d]
__device__ float g_AT[DD*DD];         // [j][d]
__device__ float g_avec[DD];
__device__ float g_WuT1[DD*DD];       // [j][d]
__device__ float g_W2[DD*DD];         // [d][j] = sum_i Wu[d][DD+i] Wv[i][j]
__device__ float g_cvec[DD];
__device__ float g_scores[BB*MM];     // [b][m]
__device__ float g_psum[NB*BB];       // [k][b]
__device__ float g_part[NB*DD*BB];    // [k][d][b]
__device__ float g_h[DD*BB];          // [j][b] (unnormalized)
__device__ float g_zinv[BB];
__device__ int   g_tk[BB*TK*3];       // row, prev, slot
__device__ int   g_count;
__device__ int   g_gen2;

// =================== init launch 1 ===================
__global__ void p_init1(const float* __restrict__ Wq, const float* __restrict__ bq,
                        const float* __restrict__ Wk, const float* __restrict__ Wv,
                        const float* __restrict__ bv, const float* __restrict__ Wu){
  int blk = blockIdx.x, tid = threadIdx.x;
  if (blk < 32){                       // WuT1[j][d] = Wu[d][j]
    int base = blk*2048;
    #pragma unroll
    for (int z=0;z<8;z++){ int e = base + z*256 + tid; int d = e>>8, j = e&255;
      g_WuT1[j*DD+d] = Wu[(size_t)d*2*DD + j]; }
  } else if (blk < 48){                // A tiles: g_AT[j][d]
    __shared__ float aq[16][68], ak[16][68];
    int tn = blk-32, j0 = (tn>>2)*64, d0 = (tn&3)*64;
    int ty = tid>>4, tx = tid&15;
    float acc[16];
    #pragma unroll
    for (int z=0;z<16;z++) acc[z]=0.f;
    for (int ib=0; ib<DD; ib+=16){
      #pragma unroll
      for (int z=0;z<4;z++){ int e = z*256+tid; int i=e>>6, j=e&63;
        aq[i][j] = Wq[(size_t)(ib+i)*DD + j0 + j];
        ak[i][j] = Wk[(size_t)(ib+i)*DD + d0 + j]; }
      __syncthreads();
      #pragma unroll
      for (int i=0;i<16;i++){
        float qv[4], kv[4];
        #pragma unroll
        for (int u=0;u<4;u++){ qv[u]=aq[i][ty*4+u]; kv[u]=ak[i][tx*4+u]; }
        #pragma unroll
        for (int jr=0;jr<4;jr++)
          #pragma unroll
          for (int dr=0;dr<4;dr++) acc[jr*4+dr] = fmaf(qv[jr], kv[dr], acc[jr*4+dr]);
      }
      __syncthreads();
    }
    #pragma unroll
    for (int jr=0;jr<4;jr++)
      #pragma unroll
      for (int dr=0;dr<4;dr++)
        g_AT[(size_t)(j0+ty*4+jr)*DD + d0+tx*4+dr] = acc[jr*4+dr]*SCALE;
  } else if (blk < 64){                // W2 tiles, stored [d][i]
    __shared__ float wv[16][68], wu[16][68];
    int tn = blk-48, i0 = (tn>>2)*64, d0 = (tn&3)*64;
    int ty = tid>>4, tx = tid&15;
    float acc[16];
    #pragma unroll
    for (int z=0;z<16;z++) acc[z]=0.f;
    for (int jb=0; jb<DD; jb+=16){
      #pragma unroll
      for (int z=0;z<4;z++){ int e = z*256+tid; int jj=e>>6, ii=e&63;
        wv[jj][ii] = Wv[(size_t)(jb+jj)*DD + i0 + ii];
        wu[jj][ii] = Wu[(size_t)(d0+ii)*2*DD + DD + jb + jj]; }
      __syncthreads();
      #pragma unroll
      for (int jj=0;jj<16;jj++){
        float vv[4], uv[4];
        #pragma unroll
        for (int u=0;u<4;u++){ vv[u]=wv[jj][ty*4+u]; uv[u]=wu[jj][tx*4+u]; }
        #pragma unroll
        for (int ir=0;ir<4;ir++)
          #pragma unroll
          for (int dr=0;dr<4;dr++) acc[ir*4+dr] = fmaf(vv[ir], uv[dr], acc[ir*4+dr]);
      }
      __syncthreads();
    }
    #pragma unroll
    for (int ir=0;ir<4;ir++)
      #pragma unroll
      for (int dr=0;dr<4;dr++)
        g_W2[(size_t)(d0+tx*4+dr)*DD + i0+ty*4+ir] = acc[ir*4+dr];
  } else if (blk < 80){                // slot map
    int base = (blk-64)*2048;
    #pragma unroll
    for (int z=0;z<8;z++) g_slot[base + z*256 + tid] = -1;
  } else if (blk == 80){
    if (tid==0){ g_count = 0; g_gen2 = 0; }
    if (tid < BB) g_ovcnt[tid] = 0;
  } else if (blk == 81){               // avec
    __shared__ float bqs[DD];
    bqs[tid] = bq[tid]; __syncthreads();
    float acc = 0.f;
    #pragma unroll 4
    for (int i=0;i<DD;i++) acc = fmaf(Wk[(size_t)i*DD+tid], bqs[i], acc);
    g_avec[tid] = acc*SCALE;
  } else if (blk == 82){               // cvec
    __shared__ float bvs[DD];
    bvs[tid] = bv[tid]; __syncthreads();
    float acc = 0.f;
    #pragma unroll 4
    for (int j=0;j<DD;j++) acc = fmaf(Wu[(size_t)tid*2*DD + DD + j], bvs[j], acc);
    g_cvec[tid] = acc;
  }
}

// =================== init launch 2: qk / gx GEMMs ===================
__global__ void p_init2(const float* __restrict__ x, const float* __restrict__ bu){
  __shared__ float xt[64][17];
  __shared__ float wt[16][68];
  int blk = blockIdx.x, tid = threadIdx.x;
  int which = blk>>6;
  int r = blk&63;
  int s0 = (r>>2)*64, d0 = (r&3)*64;
  const float* W = which ? g_WuT1 : g_AT;
  int ty = tid>>4, tx = tid&15;
  float acc[16];
  #pragma unroll
  for (int z=0;z<16;z++) acc[z]=0.f;
  for (int jb=0; jb<DD; jb+=16){
    { int ss = tid>>2, jq = tid&3;
      float4 xv = *(const float4*)&x[(size_t)(s0+ss)*DD + jb + jq*4];
      xt[ss][jq*4+0]=xv.x; xt[ss][jq*4+1]=xv.y; xt[ss][jq*4+2]=xv.z; xt[ss][jq*4+3]=xv.w; }
    #pragma unroll
    for (int z=0;z<4;z++){ int e = z*256+tid; int jj=e>>6, dd=e&63;
      wt[jj][dd] = W[(size_t)(jb+jj)*DD + d0 + dd]; }
    __syncthreads();
    #pragma unroll
    for (int jj=0;jj<16;jj++){
      float xv[4], wv4[4];
      #pragma unroll
      for (int u=0;u<4;u++){ xv[u]=xt[ty*4+u][jj]; wv4[u]=wt[jj][tx*4+u]; }
      #pragma unroll
      for (int sr=0;sr<4;sr++)
        #pragma unroll
        for (int dr=0;dr<4;dr++) acc[sr*4+dr] = fmaf(xv[sr], wv4[dr], acc[sr*4+dr]);
    }
    __syncthreads();
  }
  float* dst = which ? g_gx : g_qk;
  const float* bias = which ? bu : g_avec;
  #pragma unroll
  for (int sr=0;sr<4;sr++){
    int s = s0 + ty*4 + sr;
    int b = s>>6, t = s&63;
    size_t ro = (size_t)(t*BB+b)*DD + d0 + tx*4;
    #pragma unroll
    for (int dr=0;dr<4;dr++) dst[ro+dr] = acc[sr*4+dr] + bias[d0+tx*4+dr];
  }
}

// =================== grid barrier ===================
__device__ __forceinline__ void gbar(int target){
  __syncthreads();
  if (threadIdx.x == 0){
    int old;
    asm volatile("atom.acq_rel.gpu.global.add.s32 %0, [%1], %2;"
                 : "=r"(old) : "l"(&g_count), "r"(1) : "memory");
    if (old == target*NB - 1){
      asm volatile("st.release.gpu.global.s32 [%0], %1;"
                   :: "l"(&g_gen2), "r"(target) : "memory");
    } else {
      int g;
      do {
        asm volatile("ld.acquire.gpu.global.s32 %0, [%1];"
                     : "=r"(g) : "l"(&g_gen2) : "memory");
      } while (g < target);
    }
  }
  __syncthreads();
}

__device__ __forceinline__ float dot4acc(float4 a, float4 b, float acc){
  acc = fmaf(a.x, b.x, acc);
  acc = fmaf(a.y, b.y, acc);
  acc = fmaf(a.z, b.z, acc);
  acc = fmaf(a.w, b.w, acc);
  return acc;
}

// =================== the persistent kernel ===================
__global__ void __launch_bounds__(256, 1)
persist(const float* __restrict__ base, const float* __restrict__ x,
        const float* __restrict__ Wv, const float* __restrict__ bv,
        float* __restrict__ out){
  extern __shared__ float dsm[];
  float* rowsf = dsm;          // [16][256] base rows (persistent)
  float* qks   = dsm + 4096;   // [16][256] qk[b][j] for current t
  float* sbuf  = dsm + 8192;   // AB: spart[d][b] ; C2: hh[j][b]

  __shared__ float sc[16][17];
  __shared__ __align__(16) float esm[16][16];  // [r][b] unnormalized exp
  __shared__ int   dlist[256];
  __shared__ int   dcnt_s;
  __shared__ float warrv[8]; __shared__ int warri[8];
  __shared__ int   idxs_s[TK];
  __shared__ int   chosen_s;
  __shared__ __align__(16) float4 sred4[256];
  __shared__ float zred[4];
  __shared__ __align__(16) float wrow[4*DD];   // Wv rows dd0,dd0+1 ; W2 rows dd0,dd0+1
  __shared__ float cacc[16][4][9];
  __shared__ float sgate[16][2];
  __shared__ int   tk_s[BB*TK*3];
  __shared__ float zin_s[16];
  __shared__ float sbv[2], scv[2];

  int blk = blockIdx.x, tid = threadIdx.x;
  int m0 = blk*16;
  int wid = tid>>5, lane = tid&31;
  int dd0 = blk*2;

  // persistent loads
  for (int i=tid;i<16*DD;i+=256) rowsf[i] = base[(size_t)m0*DD + i];
  for (int i=tid;i<16*DD;i+=256) qks[i]   = g_qk[i];
  for (int i=tid;i<2*DD;i+=256){ wrow[i] = Wv[(size_t)dd0*DD + i]; wrow[2*DD+i] = g_W2[(size_t)dd0*DD + i]; }
  if (tid<2){ sbv[tid] = bv[dd0+tid]; scv[tid] = g_cvec[dd0+tid]; }

  int bid = 0;
  for (int t=0;t<SS;t++){
    // ================= Phase AB =================
    if (tid==0) dcnt_s = 0;
    __syncthreads();
    {
      int b = tid>>4, r = tid&15;
      int s = __ldcg(&g_slot[b*MM + m0 + r]);
      if (s >= 0){ int p = atomicAdd(&dcnt_s,1); dlist[p] = (b<<16)|(r<<12)|s; }
    }
    // base score GEMM 16b x 16r x 256j
    {
      int jq = tid&15, bq0 = ((tid>>4)&3)*4, r0 = (tid>>6)*4;
      float acc[16];
      #pragma unroll
      for (int zz=0;zz<16;zz++) acc[zz]=0.f;
      #pragma unroll
      for (int jj=0;jj<4;jj++){
        int jb = jj*64 + jq*4;
        float4 qa[4], ra[4];
        #pragma unroll
        for (int u=0;u<4;u++){
          qa[u] = *(const float4*)&qks[(bq0+u)*256 + jb];
          ra[u] = *(const float4*)&rowsf[(r0+u)*256 + jb];
        }
        #pragma unroll
        for (int bi=0;bi<4;bi++)
          #pragma unroll
          for (int ri=0;ri<4;ri++)
            acc[bi*4+ri] = dot4acc(qa[bi], ra[ri], acc[bi*4+ri]);
      }
      #pragma unroll
      for (int off=8; off; off>>=1){
        #pragma unroll
        for (int zz=0;zz<16;zz++) acc[zz] += __shfl_xor_sync(0xffffffffu, acc[zz], off);
      }
      if (jq==0){
        #pragma unroll
        for (int bi=0;bi<4;bi++)
          #pragma unroll
          for (int ri=0;ri<4;ri++) sc[bq0+bi][r0+ri] = acc[bi*4+ri];
      }
    }
    __syncthreads();
    int dn = dcnt_s;
    // dirty score fixes
    for (int e=wid; e<dn; e+=8){
      int pk = dlist[e]; int eb = pk>>16, er = (pk>>12)&15, es = pk&0xfff;
      const float* ov = g_ovl + ((size_t)eb*OV + es)*DD;
      float a2 = 0.f;
      #pragma unroll
      for (int k=0;k<8;k++) a2 = fmaf(__ldcg(&ov[lane+32*k]), qks[eb*256 + lane+32*k], a2);
      #pragma unroll
      for (int off=16; off; off>>=1) a2 += __shfl_xor_sync(0xffffffffu, a2, off);
      if (lane==0) sc[eb][er] = a2;
    }
    __syncthreads();
    // scores -> gmem; e = exp(s); psum
    {
      int b = tid>>4, r = tid&15;
      float sv = sc[b][r];
      __stcg(&g_scores[b*MM + m0 + r], sv);
      float e = expf(sv);
      esm[r][b] = e;
      float ps = e;
      #pragma unroll
      for (int off=8; off; off>>=1) ps += __shfl_xor_sync(0xffffffffu, ps, off);
      if (r==0) __stcg(&g_psum[blk*16 + b], ps);
    }
    __syncthreads();
    // partials: thread owns d=tid; spart[d][b]
    {
      float acc[16];
      #pragma unroll
      for (int z=0;z<16;z++) acc[z]=0.f;
      #pragma unroll
      for (int r=0;r<16;r++){
        float rv = rowsf[r*256 + tid];
        float4 e0 = *(const float4*)&esm[r][0];
        float4 e1 = *(const float4*)&esm[r][4];
        float4 e2 = *(const float4*)&esm[r][8];
        float4 e3 = *(const float4*)&esm[r][12];
        acc[0]=fmaf(e0.x,rv,acc[0]);  acc[1]=fmaf(e0.y,rv,acc[1]);
        acc[2]=fmaf(e0.z,rv,acc[2]);  acc[3]=fmaf(e0.w,rv,acc[3]);
        acc[4]=fmaf(e1.x,rv,acc[4]);  acc[5]=fmaf(e1.y,rv,acc[5]);
        acc[6]=fmaf(e1.z,rv,acc[6]);  acc[7]=fmaf(e1.w,rv,acc[7]);
        acc[8]=fmaf(e2.x,rv,acc[8]);  acc[9]=fmaf(e2.y,rv,acc[9]);
        acc[10]=fmaf(e2.z,rv,acc[10]);acc[11]=fmaf(e2.w,rv,acc[11]);
        acc[12]=fmaf(e3.x,rv,acc[12]);acc[13]=fmaf(e3.y,rv,acc[13]);
        acc[14]=fmaf(e3.z,rv,acc[14]);acc[15]=fmaf(e3.w,rv,acc[15]);
      }
      #pragma unroll
      for (int z=0;z<16;z++) sbuf[tid*16 + z] = acc[z];
      // dirty partial corrections (thread-private region; no atomics)
      for (int e2=0;e2<dn;e2++){
        int pk = dlist[e2]; int eb = pk>>16, er = (pk>>12)&15, es = pk&0xfff;
        float ev = esm[er][eb];
        float ovv = __ldcg(&g_ovl[((size_t)eb*OV + es)*DD + tid]);
        sbuf[tid*16 + eb] += ev*(ovv - rowsf[er*256 + tid]);
      }
      // store partials [k][d][b], contiguous across threads
      float4* gp4 = (float4*)g_part;
      const float4* sp4 = (const float4*)&sbuf[tid*16];
      #pragma unroll
      for (int z=0;z<4;z++) __stcg(&gp4[((size_t)blk*256 + tid)*4 + z], sp4[z]);
    }
    gbar(++bid);

    // ================= Phase C1: d-chunk h reduce; blocks<16: Z + top8 + slots =================
    {
      const float4* gp4 = (const float4*)g_part;
      int q = tid&7, k0 = tid>>3;
      float4 a4 = make_float4(0.f,0.f,0.f,0.f);
      #pragma unroll
      for (int p=0;p<4;p++){
        float4 v = __ldcg(&gp4[(size_t)(k0 + p*32)*1024 + dd0*4 + q]);
        a4.x += v.x; a4.y += v.y; a4.z += v.z; a4.w += v.w;
      }
      sred4[tid] = a4;
      __syncthreads();
      #pragma unroll
      for (int off=128; off>=8; off>>=1){
        if (tid < off){
          float4 o = sred4[tid+off]; float4 m = sred4[tid];
          m.x+=o.x; m.y+=o.y; m.z+=o.z; m.w+=o.w;
          sred4[tid] = m;
        }
        __syncthreads();
      }
      if (tid < 8) __stcg(&((float4*)g_h)[dd0*4 + tid], sred4[tid]);
    }
    // prefetch qk for t+1 (safe: AB use of qks done before bar)
    if (t+1 < SS){
      const float* qsrc = g_qk + (size_t)(t+1)*BB*DD;
      for (int i=tid;i<16*DD;i+=256) qks[i] = qsrc[i];
    }
    if (blk < BB){
      int b2 = blk;
      float zp = (tid < NB) ? __ldcg(&g_psum[tid*16 + b2]) : 0.f;
      #pragma unroll
      for (int off=16; off; off>>=1) zp += __shfl_xor_sync(0xffffffffu, zp, off);
      if (lane==0 && wid<4) zred[wid] = zp;
      __syncthreads();
      if (tid==0) __stcg(&g_zinv[b2], 1.0f/(zred[0]+zred[1]+zred[2]+zred[3]));
      if (t < SS-1){
        // top-8
        float4 va = __ldcg((const float4*)&g_scores[b2*MM + tid*8]);
        float4 vb = __ldcg((const float4*)&g_scores[b2*MM + tid*8 + 4]);
        float vloc[8] = {va.x,va.y,va.z,va.w,vb.x,vb.y,vb.z,vb.w};
        int base_m = tid*8;
        for (int round=0; round<TK; round++){
          float v = -FLT_MAX; int bi2 = MM;
          #pragma unroll
          for (int k=0;k<8;k++){ if (vloc[k] > v){ v = vloc[k]; bi2 = base_m+k; } }
          #pragma unroll
          for (int off=16; off; off>>=1){
            float ov2 = __shfl_xor_sync(0xffffffffu, v, off);
            int   oi  = __shfl_xor_sync(0xffffffffu, bi2, off);
            if (ov2 > v || (ov2==v && oi<bi2)){ v=ov2; bi2=oi; }
          }
          if (lane==0){ warrv[wid]=v; warri[wid]=bi2; }
          __syncthreads();
          if (tid==0){
            float bv2 = warrv[0]; int bj = warri[0];
            for (int w=1;w<8;w++){
              if (warrv[w]>bv2 || (warrv[w]==bv2 && warri[w]<bj)){ bv2=warrv[w]; bj=warri[w]; }
            }
            idxs_s[round] = bj; chosen_s = bj;
          }
          __syncthreads();
          int ch = chosen_s;
          if ((ch>>3) == tid) vloc[ch&7] = -FLT_MAX;
        }
        if (tid==0){
          int cnt = __ldcg(&g_ovcnt[b2]);
          for (int i=0;i<TK;i++){
            int row = idxs_s[i];
            int s = __ldcg(&g_slot[b2*MM+row]);
            int prev = s;
            if (s < 0){ s = cnt++; __stcg(&g_slot[b2*MM+row], s); }
            __stcg(&g_tk[b2*24 + i*3 + 0], row);
            __stcg(&g_tk[b2*24 + i*3 + 1], prev);
            __stcg(&g_tk[b2*24 + i*3 + 2], s);
          }
          __stcg(&g_ovcnt[b2], cnt);
        }
      }
    }
    gbar(++bid);

    // ================= Phase C2: GEMV (weights smem-resident) + out + gate + updates =================
    {
      const float4* h4g = (const float4*)g_h;
      float4* s4 = (float4*)sbuf;
      for (int i=tid;i<1024;i+=256) s4[i] = __ldcg(&h4g[i]);
      if (tid < 16) zin_s[tid] = __ldcg(&g_zinv[tid]);
      if (t < SS-1){
        for (int i=tid;i<BB*TK*3;i+=256) tk_s[i] = __ldcg(&g_tk[i]);
      }
      __syncthreads();
      // GEMV: thread = (jseg=tid>>4, b=tid&15); 4 accs = mo_d0, mo_d1, gp_d0, gp_d1
      {
        int b = tid&15, jseg = tid>>4;
        float a0=0.f, a1=0.f, a2=0.f, a3=0.f;
        #pragma unroll
        for (int jj=0;jj<16;jj++){
          int j = jseg*16 + jj;
          float hv = sbuf[j*16 + b];
          a0 = fmaf(wrow[j],        hv, a0);
          a1 = fmaf(wrow[256 + j],  hv, a1);
          a2 = fmaf(wrow[512 + j],  hv, a2);
          a3 = fmaf(wrow[768 + j],  hv, a3);
        }
        a0 += __shfl_xor_sync(0xffffffffu, a0, 16);
        a1 += __shfl_xor_sync(0xffffffffu, a1, 16);
        a2 += __shfl_xor_sync(0xffffffffu, a2, 16);
        a3 += __shfl_xor_sync(0xffffffffu, a3, 16);
        if ((tid&16)==0){
          cacc[b][0][wid]=a0; cacc[b][1][wid]=a1; cacc[b][2][wid]=a2; cacc[b][3][wid]=a3;
        }
      }
      __syncthreads();
      if (tid < 64){
        int b = tid&15, o = tid>>4;
        float s = 0.f;
        #pragma unroll
        for (int w=0;w<8;w++) s += cacc[b][o][w];
        float zi = zin_s[b];
        if (o < 2){
          out[((size_t)b*SS+t)*DD + dd0 + o] = s*zi + sbv[o];
        } else {
          int di = o-2;
          float gg = s*zi + scv[di] + __ldg(&g_gx[((size_t)t*BB+b)*DD + dd0 + di]);
          sgate[b][di] = 1.0f/(1.0f+expf(-gg));
        }
      }
      __syncthreads();
      // row updates for this d-chunk (skip last step)
      if (t < SS-1){
        int ent = tid>>1, di = tid&1;
        int b = ent>>3, i = ent&7;
        int row  = tk_s[(b*TK+i)*3 + 0];
        int prev = tk_s[(b*TK+i)*3 + 1];
        int slot = tk_s[(b*TK+i)*3 + 2];
        int d = dd0 + di;
        float old = (prev < 0) ? __ldg(&base[(size_t)row*DD + d])
                               : __ldcg(&g_ovl[((size_t)b*OV + prev)*DD + d]);
        float g = sgate[b][di];
        float xd = __ldg(&x[((size_t)b*SS+t)*DD + d]);
        __stcg(&g_ovl[((size_t)b*OV + slot)*DD + d], old + g*(xd - old));
      }
    }
    gbar(++bid);
  }
}

// =================== launch ===================
extern "C" void kernel_launch(void* const* d_in, const int* in_sizes, int n_in,
                              void* d_out, int out_size){
  const float* x      = (const float*)d_in[0];
  const float* memory = (const float*)d_in[1];
  const float* Wq     = (const float*)d_in[2];
  const float* bq     = (const float*)d_in[3];
  const float* Wk     = (const float*)d_in[4];
  // bk contributes only a softmax-invariant constant -> dropped
  const float* Wv     = (const float*)d_in[6];
  const float* bv     = (const float*)d_in[7];
  const float* Wu     = (const float*)d_in[8];
  const float* bu     = (const float*)d_in[9];
  float* out = (float*)d_out;

  static int attr_done = 0;
  if (!attr_done){
    cudaFuncSetAttribute(persist, cudaFuncAttributeMaxDynamicSharedMemorySize, 49152);
    attr_done = 1;
  }

  p_init1<<<NB, 256>>>(Wq, bq, Wk, Wv, bv, Wu);
  p_init2<<<NB, 256>>>(x, bu);
  persist<<<NB, 256, 49152>>>(memory, x, Wv, bv, out);
}